// round 9
// baseline (speedup 1.0000x reference)
#include <cuda_runtime.h>
#include <math.h>

// ---------------------------------------------------------------------------
// Problem constants
// ---------------------------------------------------------------------------
#define B_   2
#define P_   4000
#define NP_  4096
#define D_   64
#define M_   512
#define NX_  432
#define NY_  496
#define HW_  (NX_ * NY_)          // 214272
#define BITW (HW_ / 32)           // 6696 bitmap words per batch

#define S0_   ((size_t)B_ * 128 * HW_)
#define S2_   ((size_t)B_ * 64 * HW_)
#define OFF1_ (S0_)
#define OFF2_ (2 * S0_)
#define OFF3_ (2 * S0_ + S2_)                        // floats in the dense grids
#define OFF4_ (OFF3_ + (size_t)B_ * P_ * D_)

// Tiling / schedule
#define TILE_P 64
#define TILE_T 64
#define CH2    2                        // point chunks
#define CPTS2  (NP_ / CH2)              // 2048
#define PITCH  68
#define NTHR   256
#define PTILES 63                       // ceil(4000/64)
#define N_PTI  (PTILES * B_ * CH2)      // 252 point items  (63*2*2)
#define N_MEMI (PTILES * B_)            // 126 memory items
#define N_ATTN (N_PTI + N_MEMI)         // 378
#define NZ     210                      // zero stripes
#define NITEMS (N_ATTN + NZ)            // 588 = 42 groups of (5 zero + 9 attn)
#define GRID_F 444                      // 148 SMs x 3 resident
#define PLANE4 (HW_ / 4)                // 53568 float4 per plane
#define N4_    ((size_t)640 * PLANE4)   // 34,283,520 float4 to fill
#define ZCHUNK 163255                   // ceil(N4_/NZ)

// dynamic shared layout (bytes) -- attn roles
#define SM_PL   0                                   // 64*68*4   = 17408
#define SM_PT   17408                               // 2*64*68*4 = 34816
#define SM_TKV  52224                               // 64*8*4    =  2048
#define SM_TKI  54272                               // 64*8*4    =  2048
#define SMEM_BYTES 56320                            // zero role: bitmap 53568B fits

__device__ int      g_winner[B_ * HW_];
__device__ unsigned g_bitmap[B_ * BITW];
__device__ unsigned g_ctr;
__device__ float    g_pkv[B_ * P_ * 16];            // 2 chunks x 8 candidates
__device__ int      g_pki[B_ * P_ * 16];

// ---------------------------------------------------------------------------
__device__ __forceinline__ void cp16(void* dst, const void* src) {
    unsigned a = (unsigned)__cvta_generic_to_shared(dst);
    asm volatile("cp.async.cg.shared.global [%0], [%1], 16;" :: "r"(a), "l"(src));
}
__device__ __forceinline__ void cp_commit() {
    asm volatile("cp.async.commit_group;" ::: "memory");
}
__device__ __forceinline__ void cp_wait_all() {
    asm volatile("cp.async.wait_group 0;" ::: "memory");
}
__device__ __forceinline__ void fma2(unsigned long long& acc,
                                     unsigned long long a, unsigned long long b) {
    asm volatile("fma.rn.f32x2 %0, %1, %2, %0;" : "+l"(acc) : "l"(a), "l"(b));
}

// ---------------------------------------------------------------------------
// Core: 64 pillars x npts candidates -> per-pillar top-8 in s_tkv/s_tki.
// 8 warps; warp wy owns pillars [wy*8, wy*8+8). Lane tx owns candidate rows
// {tx, tx+32}. 8x2 microtile, packed-f32x2 FMA, cp.async double buffer.
// ---------------------------------------------------------------------------
__device__ void attn_core(const float* __restrict__ pb,
                          const float* __restrict__ vb,
                          int idx_base, int pvalid, int npts, char* smem)
{
    float* s_pl  = (float*)(smem + SM_PL);
    float* s_pt  = (float*)(smem + SM_PT);
    float* s_tkv = (float*)(smem + SM_TKV);
    int*   s_tki = (int*)(smem + SM_TKI);

    const int t  = threadIdx.x;
    const int tx = t & 31;
    const int wy = t >> 5;
    const unsigned FULL = 0xffffffffu;

    s_tkv[t]       = -INFINITY;
    s_tkv[t + 256] = -INFINITY;

#pragma unroll
    for (int q = 0; q < 4; ++q) {
        int lin = t + q * NTHR;
        int r = lin >> 4, c = (lin & 15) << 2;
        cp16(s_pt + r * PITCH + c, vb + r * D_ + c);
    }
    cp_commit();

#pragma unroll
    for (int q = 0; q < 4; ++q) {
        int lin = t + q * NTHR;
        int r = lin >> 4, c = (lin & 15) << 2;
        float4 v = make_float4(0.f, 0.f, 0.f, 0.f);
        if (r < pvalid) v = *(const float4*)(pb + r * D_ + c);
        *(float4*)(s_pl + r * PITCH + c) = v;
    }
    __syncthreads();

    float vmin[8];
#pragma unroll
    for (int i = 0; i < 8; ++i) vmin[i] = -INFINITY;

    const int NT = npts / TILE_T;
    for (int tile = 0; tile < NT; ++tile) {
        float* buf = s_pt + (tile & 1) * (TILE_T * PITCH);
        cp_wait_all();
        __syncthreads();
        if (tile + 1 < NT) {
            float* nb = s_pt + ((tile + 1) & 1) * (TILE_T * PITCH);
            const float* src = vb + (size_t)(tile + 1) * TILE_T * D_;
#pragma unroll
            for (int q = 0; q < 4; ++q) {
                int lin = t + q * NTHR;
                int r = lin >> 4, c = (lin & 15) << 2;
                cp16(nb + r * PITCH + c, src + r * D_ + c);
            }
            cp_commit();
        }

        unsigned long long acc[8][2];
#pragma unroll
        for (int i = 0; i < 8; ++i) { acc[i][0] = 0ull; acc[i][1] = 0ull; }

        const float* prow = s_pl + (wy << 3) * PITCH;
#pragma unroll 4
        for (int dc = 0; dc < D_; dc += 4) {
            ulonglong2 xv0 = *(const ulonglong2*)(buf + tx * PITCH + dc);
            ulonglong2 xv1 = *(const ulonglong2*)(buf + (tx + 32) * PITCH + dc);
#pragma unroll
            for (int i = 0; i < 8; ++i) {
                ulonglong2 av = *(const ulonglong2*)(prow + i * PITCH + dc);
                fma2(acc[i][0], av.x, xv0.x);
                fma2(acc[i][1], av.x, xv1.x);
                fma2(acc[i][0], av.y, xv0.y);
                fma2(acc[i][1], av.y, xv1.y);
            }
        }

        const int base = idx_base + tile * TILE_T;
#pragma unroll
        for (int i = 0; i < 8; ++i) {
            const int pr = (wy << 3) + i;
            float thr = vmin[i];
            float s0, s1;
            {
                unsigned long long v = acc[i][0];
                s0 = __uint_as_float((unsigned)v) +
                     __uint_as_float((unsigned)(v >> 32));
                v = acc[i][1];
                s1 = __uint_as_float((unsigned)v) +
                     __uint_as_float((unsigned)(v >> 32));
            }
            unsigned any = __ballot_sync(FULL, (s0 > thr) | (s1 > thr));
            if (any) {
                float* tv = s_tkv + pr * 8;
                int*   ti = s_tki + pr * 8;
#pragma unroll
                for (int j = 0; j < 2; ++j) {
                    float sj = j ? s1 : s0;
                    unsigned m = __ballot_sync(FULL, sj > thr);
                    while (m) {
                        int ln = __ffs(m) - 1; m &= m - 1;
                        float v = __shfl_sync(FULL, sj, ln);
                        if (v > thr) {
                            int slot = 0; float mn = tv[0];
#pragma unroll
                            for (int k = 1; k < 8; ++k) {
                                float x = tv[k];
                                if (x < mn) { mn = x; slot = k; }
                            }
                            tv[slot] = v;
                            ti[slot] = base + ln + 32 * j;
                            thr = tv[0];
#pragma unroll
                            for (int k = 1; k < 8; ++k) thr = fminf(thr, tv[k]);
                        }
                    }
                }
                vmin[i] = thr;
            }
        }
    }
    __syncwarp();
}

// ---------------------------------------------------------------------------
// Zero stripe with winner materialization (static planes) via smem bitmap.
// Planes: [0,256) out0, [256,512) out1 (ch<64 = pillars; ch>=64 zeroed here,
// overwritten by pos_scatter); [512,640) out2 = scale.
// ---------------------------------------------------------------------------
__device__ void zero_item(int zid, const float* __restrict__ pillars,
                          const float* __restrict__ scale,
                          float* __restrict__ out, char* smem)
{
    unsigned* s_bm = (unsigned*)smem;
    const int t = threadIdx.x;
    for (int i = t; i < B_ * BITW; i += NTHR) s_bm[i] = g_bitmap[i];
    __syncthreads();

    size_t beg = (size_t)zid * ZCHUNK;
    size_t end = beg + ZCHUNK; if (end > N4_) end = N4_;
    float4* o4 = (float4*)out;

    for (size_t f = beg + t; f < end; f += NTHR) {
        int plane = (int)(f / PLANE4);          // 0..639
        int col4  = ((int)(f - (size_t)plane * PLANE4)) << 2;
        float4 v = make_float4(0.f, 0.f, 0.f, 0.f);
        int b, ch;
        const float* src;
        bool stat;
        if (plane < 512) {
            int pl = plane & 255;
            b = pl >> 7; ch = pl & 127;
            stat = ch < 64; src = pillars;
        } else {
            int pl = plane - 512;
            b = pl >> 6; ch = pl & 63;
            stat = true; src = scale;
        }
        if (stat) {
            unsigned bits = (s_bm[b * BITW + (col4 >> 5)] >> (col4 & 31)) & 0xFu;
            if (bits) {
                int colb = b * HW_ + col4;
                if (bits & 1u) { int w = g_winner[colb];     v.x = src[((size_t)(b * P_ + w)) * D_ + ch]; }
                if (bits & 2u) { int w = g_winner[colb + 1]; v.y = src[((size_t)(b * P_ + w)) * D_ + ch]; }
                if (bits & 4u) { int w = g_winner[colb + 2]; v.z = src[((size_t)(b * P_ + w)) * D_ + ch]; }
                if (bits & 8u) { int w = g_winner[colb + 3]; v.w = src[((size_t)(b * P_ + w)) * D_ + ch]; }
            }
        }
        __stcs(o4 + f, v);
    }
}

// ---------------------------------------------------------------------------
// Persistent fused kernel: 444 blocks pull items from a queue.
// 42 groups of 14 items: id%14 < 5 -> zero stripe, else attention item.
//   zero  zid = (id/14)*5 + id%14              (210 total)
//   attn  aid = (id/14)*9 + (id%14 - 5)        (378 total)
// attn item: [0,252) point chunk (chunk-major), [252,378) memory tile.
// ---------------------------------------------------------------------------
__global__ void __launch_bounds__(NTHR, 3)
fused_kernel(const float* __restrict__ pillars,
             const float* __restrict__ scale,
             const float* __restrict__ points,
             const float* __restrict__ W,
             float* __restrict__ out)
{
    extern __shared__ char smem[];
    __shared__ int s_item;
    const int t  = threadIdx.x;
    const int tx = t & 31;
    const int wy = t >> 5;
    float* s_tkv = (float*)(smem + SM_TKV);
    int*   s_tki = (int*)(smem + SM_TKI);

    for (;;) {
        __syncthreads();
        if (t == 0) s_item = (int)atomicAdd(&g_ctr, 1u);
        __syncthreads();
        const int id = s_item;
        if (id >= NITEMS) return;

        const int grp = id / 14;
        const int lane = id % 14;
        if (lane < 5) {
            zero_item(grp * 5 + lane, pillars, scale, out, smem);
            continue;
        }
        const int aid = grp * 9 + (lane - 5);
        if (aid < N_PTI) {
            // ---- point chunk: partial top-8 -> scratch
            const int chunk = aid / (PTILES * B_);      // 0 or 1
            const int pid   = aid % (PTILES * B_);
            const int b     = pid / PTILES;
            const int p0    = (pid % PTILES) * TILE_P;
            const int pvalid = min(TILE_P, P_ - p0);
            const float* pb = pillars + ((size_t)b * P_ + p0) * D_;
            const float* vb = points + ((size_t)b * NP_ + (size_t)chunk * CPTS2) * D_;
            attn_core(pb, vb, chunk * CPTS2, pvalid, CPTS2, smem);

            const int bp0 = b * P_ + p0;
#pragma unroll 1
            for (int i = 0; i < 8; ++i) {
                const int pr = (wy << 3) + i;
                if (pr >= pvalid) break;
                if (tx < 8) {
                    g_pkv[(size_t)(bp0 + pr) * 16 + chunk * 8 + tx] = s_tkv[pr * 8 + tx];
                    g_pki[(size_t)(bp0 + pr) * 16 + chunk * 8 + tx] = s_tki[pr * 8 + tx];
                }
            }
        } else {
            // ---- memory tile: single pass over 512, full epilogue
            const int mid = aid - N_PTI;
            const int b   = mid / PTILES;
            const int p0  = (mid % PTILES) * TILE_P;
            const int pvalid = min(TILE_P, P_ - p0);
            const float* pb = pillars + ((size_t)b * P_ + p0) * D_;
            attn_core(pb, W, 0, pvalid, M_, smem);

#pragma unroll 1
            for (int i = 0; i < 8; ++i) {
                const int pr = (wy << 3) + i;
                if (pr >= pvalid) break;
                float vals[8]; int id8[8];
#pragma unroll
                for (int k = 0; k < 8; ++k) {
                    vals[k] = s_tkv[pr * 8 + k]; id8[k] = s_tki[pr * 8 + k];
                }
                float mx = vals[0];
#pragma unroll
                for (int k = 1; k < 8; ++k) mx = fmaxf(mx, vals[k]);
                float w[8], ssum = 0.f;
#pragma unroll
                for (int k = 0; k < 8; ++k) { w[k] = expf(vals[k] - mx); ssum += w[k]; }
                float inv = 1.f / ssum;
                float a0 = 0.f, a1 = 0.f;
#pragma unroll
                for (int k = 0; k < 8; ++k) {
                    const float* vp = W + (size_t)id8[k] * D_;
                    float wk = w[k] * inv;
                    a0 += wk * vp[tx];
                    a1 += wk * vp[tx + 32];
                }
                float* op = out + OFF4_ + ((size_t)b * P_ + p0 + pr) * D_;
                op[tx] = a0;
                op[tx + 32] = a1;
            }
        }
    }
}

// ---------------------------------------------------------------------------
// merge16: one warp per pillar merges 2x8 candidates -> top-8, softmax,
// weighted gather, writes dense pos_point (out3).
// ---------------------------------------------------------------------------
__global__ void __launch_bounds__(256)
merge_kernel(const float* __restrict__ points, float* __restrict__ out)
{
    const int w  = blockIdx.x * 8 + (threadIdx.x >> 5);
    const int tx = threadIdx.x & 31;
    if (w >= B_ * P_) return;
    const unsigned FULL = 0xffffffffu;
    const int b = w / P_;
    const float* vb = points + (size_t)b * NP_ * D_;

    float v = (tx < 16) ? g_pkv[(size_t)w * 16 + tx] : -INFINITY;
    int   ii = (tx < 16) ? g_pki[(size_t)w * 16 + tx] : 0;

    float vals[8]; int ids[8];
#pragma unroll
    for (int k = 0; k < 8; ++k) {
        float m = v;
#pragma unroll
        for (int off = 16; off; off >>= 1)
            m = fmaxf(m, __shfl_xor_sync(FULL, m, off));
        unsigned ball = __ballot_sync(FULL, v == m);
        int ln = __ffs(ball) - 1;
        ids[k] = __shfl_sync(FULL, ii, ln);
        vals[k] = m;
        if (tx == ln) v = -INFINITY;
    }

    float mx = vals[0];
#pragma unroll
    for (int k = 1; k < 8; ++k) mx = fmaxf(mx, vals[k]);
    float wt[8], ssum = 0.f;
#pragma unroll
    for (int k = 0; k < 8; ++k) { wt[k] = expf(vals[k] - mx); ssum += wt[k]; }
    float inv = 1.f / ssum;
    float a0 = 0.f, a1 = 0.f;
#pragma unroll
    for (int k = 0; k < 8; ++k) {
        const float* vp = vb + (size_t)ids[k] * D_;
        float wk = wt[k] * inv;
        a0 += wk * vp[tx];
        a1 += wk * vp[tx + 32];
    }
    float* op = out + OFF3_ + (size_t)w * D_;
    op[tx] = a0;
    op[tx + 32] = a1;
}

// ---------------------------------------------------------------------------
// pre1: clear winner / bitmap / queue counter.  pre2: build winner + bitmap.
// ---------------------------------------------------------------------------
__global__ void pre1_kernel() {
    int i = blockIdx.x * blockDim.x + threadIdx.x;
    if (i < B_ * HW_) g_winner[i] = -1;
    if (i < B_ * BITW) g_bitmap[i] = 0u;
    if (i == 0) g_ctr = 0u;
}
__global__ void pre2_kernel(const int* __restrict__ idx) {
    int i = blockIdx.x * blockDim.x + threadIdx.x;
    if (i < B_ * P_) {
        int b = i / P_;
        int col = idx[i];
        atomicMax(&g_winner[b * HW_ + col], i - b * P_);
        atomicOr(&g_bitmap[b * BITW + (col >> 5)], 1u << (col & 31));
    }
}

// ---------------------------------------------------------------------------
// pos_scatter: winner pillars write pos_mem -> out0 upper, pos_point -> out1
// upper. One warp per pillar, grid-stride.
// ---------------------------------------------------------------------------
__global__ void __launch_bounds__(256)
pos_scatter_kernel(const int* __restrict__ idx, float* __restrict__ out)
{
    const int warp0 = blockIdx.x * 8 + (threadIdx.x >> 5);
    const int tx = threadIdx.x & 31;
    for (int bp = warp0; bp < B_ * P_; bp += gridDim.x * 8) {
        int b = (bp >= P_) ? 1 : 0;
        int p = bp - b * P_;
        int col = idx[bp];
        if (g_winner[b * HW_ + col] != p) continue;
        float mv0 = out[OFF4_ + (size_t)bp * D_ + tx];
        float mv1 = out[OFF4_ + (size_t)bp * D_ + tx + 32];
        float qv0 = out[OFF3_ + (size_t)bp * D_ + tx];
        float qv1 = out[OFF3_ + (size_t)bp * D_ + tx + 32];
        size_t g0 = (size_t)b * 128 * HW_ + (size_t)(64 + tx) * HW_ + col;
        out[g0] = mv0;
        out[g0 + (size_t)32 * HW_] = mv1;
        out[OFF1_ + g0] = qv0;
        out[OFF1_ + g0 + (size_t)32 * HW_] = qv1;
    }
}

// ---------------------------------------------------------------------------
extern "C" void kernel_launch(void* const* d_in, const int* in_sizes, int n_in,
                              void* d_out, int out_size) {
    (void)in_sizes; (void)n_in; (void)out_size;
    const float* pillars = (const float*)d_in[0];
    const float* scale   = (const float*)d_in[1];
    const float* points  = (const float*)d_in[2];
    const float* W       = (const float*)d_in[3];
    const int*   idx     = (const int*)d_in[4];
    float* out = (float*)d_out;

    cudaFuncSetAttribute(fused_kernel,
                         cudaFuncAttributeMaxDynamicSharedMemorySize, SMEM_BYTES);

    pre1_kernel<<<(B_ * HW_ + 255) / 256, 256>>>();
    pre2_kernel<<<(B_ * P_ + 255) / 256, 256>>>(idx);
    fused_kernel<<<GRID_F, NTHR, SMEM_BYTES>>>(pillars, scale, points, W, out);
    merge_kernel<<<(B_ * P_ + 7) / 8, 256>>>(points, out);
    pos_scatter_kernel<<<125, 256>>>(idx, out);
}